// round 5
// baseline (speedup 1.0000x reference)
#include <cuda_runtime.h>
#include <mma.h>

using namespace nvcuda;

// Problem constants (fixed by the reference)
#define NATOMS  50000
#define EMB     256
#define PIN     64
#define POUT    64
#define NRBF    16
#define KMAXN   32
#define NEDGES  1600000
#define NPAD    50048          // 391 * 128

#define AT      32             // atoms per fused block
#define LDP     1028           // P row stride (floats); 1028 % 32 == 4 -> 2-way max
#define LDX     68             // xs row stride
#define LDR     36             // rb row stride
#define LDBS    68             // W chunk row stride

// fused-kernel dynamic smem: P[AT][LDP] + union(xs[8][32*LDX] + rbs[8][16*LDR] | Bs[64][LDBS])
#define SMEM_FLOATS (AT*LDP + 8*KMAXN*LDX + 8*NRBF*LDR)
#define SMEM_BYTES  (SMEM_FLOATS * 4)

// Scratch (device globals — no allocation allowed)
__device__ float g_xb[NPAD * PIN];        // silu(h @ W_down), pad rows zero
__device__ int   g_win[NATOMS * KMAXN];   // winning edge id
__device__ float g_h2[NPAD * POUT];       // bilinear result, pad rows zero

__device__ __forceinline__ float silu_f(float x) {
    return x / (1.0f + __expf(-x));
}

__device__ __forceinline__ void tf32x4(float4& v) {
    v.x = wmma::__float_to_tf32(v.x);
    v.y = wmma::__float_to_tf32(v.y);
    v.z = wmma::__float_to_tf32(v.z);
    v.w = wmma::__float_to_tf32(v.w);
}

// ---------------------------------------------------------------------------
// Phase A: deterministic "last update wins" scatter (matches XLA .at[].set)
// ---------------------------------------------------------------------------
__global__ void init_win_kernel() {
    int i = blockIdx.x * blockDim.x + threadIdx.x;
    if (i < NATOMS * KMAXN) g_win[i] = -1;
}

__global__ void scatter_win_kernel(const int* __restrict__ ei,
                                   const int* __restrict__ tni,
                                   int es, int ts)
{
    int e = blockIdx.x * blockDim.x + threadIdx.x;
    if (e >= NEDGES) return;
    int dst = ei[(size_t)(NEDGES + e) * es];   // edge_index[1][e]
    int k   = tni[(size_t)e * ts];             // target_neighbor_idx[e]
    if ((unsigned)dst < NATOMS && (unsigned)k < KMAXN)
        atomicMax(&g_win[dst * KMAXN + k], e);
}

// ---------------------------------------------------------------------------
// tf32 wmma GEMM core (for GEMM1 / GEMM3): unchanged from R4
// ---------------------------------------------------------------------------
template<bool SILU, bool SCALE>
__device__ __forceinline__
void wgemm_core(const float* __restrict__ A, const float* __restrict__ B,
                float* __restrict__ C, int Mload, int Mstore,
                int ldb, int ldc, int K, const float* __restrict__ scale_p)
{
    constexpr int BM = 128, BN = 64, BK = 32;
    constexpr int LDA_ = BK + 4;
    constexpr int LDB_ = BN + 4;

    __shared__ __align__(16) float sraw[BM * LDB_];
    float* As = sraw;
    float* Bs = sraw + BM * LDA_;
    float* Cs = sraw;

    const int t  = threadIdx.x;
    const int m0 = blockIdx.y * BM;
    const int n0 = blockIdx.x * BN;
    const int warp = t >> 5;
    const int wm = (warp >> 1) * 32;
    const int wn = (warp & 1) * 32;

    wmma::fragment<wmma::accumulator, 16, 16, 8, float> c[2][2];
#pragma unroll
    for (int i = 0; i < 2; i++)
#pragma unroll
        for (int j = 0; j < 2; j++) wmma::fill_fragment(c[i][j], 0.0f);

    for (int k0 = 0; k0 < K; k0 += BK) {
#pragma unroll
        for (int i = 0; i < 4; i++) {
            int row = (t >> 3) + i * 32;
            int col = (t & 7) * 4;
            float4 v = make_float4(0.f, 0.f, 0.f, 0.f);
            int gm = m0 + row;
            if (gm < Mload)
                v = *reinterpret_cast<const float4*>(A + (size_t)gm * K + k0 + col);
            tf32x4(v);
            *reinterpret_cast<float4*>(As + row * LDA_ + col) = v;
        }
#pragma unroll
        for (int i = 0; i < 2; i++) {
            int row = (t >> 4) + i * 16;
            int col = (t & 15) * 4;
            float4 v = *reinterpret_cast<const float4*>(B + (size_t)(k0 + row) * ldb + n0 + col);
            tf32x4(v);
            *reinterpret_cast<float4*>(Bs + row * LDB_ + col) = v;
        }
        __syncthreads();

#pragma unroll
        for (int kk = 0; kk < BK; kk += 8) {
            wmma::fragment<wmma::matrix_a, 16, 16, 8, wmma::precision::tf32, wmma::row_major> a[2];
            wmma::fragment<wmma::matrix_b, 16, 16, 8, wmma::precision::tf32, wmma::row_major> b[2];
#pragma unroll
            for (int i = 0; i < 2; i++)
                wmma::load_matrix_sync(a[i], As + (wm + i * 16) * LDA_ + kk, LDA_);
#pragma unroll
            for (int j = 0; j < 2; j++)
                wmma::load_matrix_sync(b[j], Bs + kk * LDB_ + wn + j * 16, LDB_);
#pragma unroll
            for (int i = 0; i < 2; i++)
#pragma unroll
                for (int j = 0; j < 2; j++)
                    wmma::mma_sync(c[i][j], a[i], b[j], c[i][j]);
        }
        __syncthreads();
    }

    const float s = SCALE ? *scale_p : 1.0f;
#pragma unroll
    for (int i = 0; i < 2; i++)
#pragma unroll
        for (int j = 0; j < 2; j++)
#pragma unroll
            for (int e = 0; e < c[i][j].num_elements; e++) {
                float v = c[i][j].x[e] * s;
                if (SILU) v = silu_f(v);
                c[i][j].x[e] = v;
            }

    if (m0 + BM <= Mstore) {
#pragma unroll
        for (int i = 0; i < 2; i++)
#pragma unroll
            for (int j = 0; j < 2; j++)
                wmma::store_matrix_sync(C + (size_t)(m0 + wm + i * 16) * ldc + n0 + wn + j * 16,
                                        c[i][j], ldc, wmma::mem_row_major);
    } else {
#pragma unroll
        for (int i = 0; i < 2; i++)
#pragma unroll
            for (int j = 0; j < 2; j++)
                wmma::store_matrix_sync(Cs + (wm + i * 16) * LDB_ + wn + j * 16,
                                        c[i][j], LDB_, wmma::mem_row_major);
        __syncthreads();
        for (int idx = t; idx < BM * BN; idx += 256) {
            int r = idx >> 6, cc = idx & 63;
            if (m0 + r < Mstore)
                C[(size_t)(m0 + r) * ldc + n0 + cc] = Cs[r * LDB_ + cc];
        }
    }
}

// GEMM1: g_xb = silu(h @ W_down)     [50000,256] x [256,64] -> padded rows = 0
__global__ __launch_bounds__(256)
void gemm1_kernel(const float* __restrict__ h, const float* __restrict__ W_down) {
    wgemm_core<true, false>(h, W_down, g_xb, NATOMS, NPAD, PIN, PIN, EMB, nullptr);
}

// GEMM3: out = silu(g_h2 @ W_up)     [NPAD,64] x [64,256], store 50000 rows
__global__ __launch_bounds__(256)
void gemm3_kernel(const float* __restrict__ W_up, float* __restrict__ out) {
    wgemm_core<true, false>(g_h2, W_up, out, NPAD, NATOMS, EMB, EMB, POUT, nullptr);
}

// ---------------------------------------------------------------------------
// FUSED kernel: per block, 32 atoms.
//  Stage 1: per-warp (4 atoms each) gather + rb[16,32]@xs[32,64] -> P in smem
//  Stage 2: block GEMM  P[32,1024] @ W_bil[1024,64] * scale -> g_h2
// ---------------------------------------------------------------------------
__global__ __launch_bounds__(256)
void fused_kernel(const float* __restrict__ rad, const int* __restrict__ ei,
                  const float* __restrict__ W_bil, const float* __restrict__ scale_p,
                  int es)
{
    extern __shared__ __align__(16) float smem[];
    float* P = smem;                           // [AT][LDP]
    float* U = smem + AT * LDP;                // union region

    const int t    = threadIdx.x;
    const int w    = t >> 5;
    const int lane = t & 31;
    const int atom0 = blockIdx.x * AT;

    // ---------------- stage 1 ----------------
    {
        float* xs  = U + w * (KMAXN * LDX);
        float* rbs = U + 8 * (KMAXN * LDX) + w * (NRBF * LDR);

        for (int i = 0; i < 4; i++) {
            const int atom = atom0 + w * 4 + i;

            // winning src per neighbor slot (lane = slot)
            int src = -1;
            if (atom < NATOMS) {
                int e = g_win[atom * KMAXN + lane];
                if (e >= 0) {
                    int s = ei[(size_t)e * es];   // edge_index[0][e]
                    if ((unsigned)s < NATOMS) src = s;
                }
            }

            // stage rb [16][32] -> rbs padded (tf32)
#pragma unroll
            for (int j = 0; j < 4; j++) {
                int g = (lane + 32 * j) * 4;          // 0..508 step 4
                int r = g >> 5, k = g & 31;
                float4 v = make_float4(0.f, 0.f, 0.f, 0.f);
                if (atom < NATOMS)
                    v = *reinterpret_cast<const float4*>(rad + (size_t)atom * NRBF * KMAXN + g);
                tf32x4(v);
                *reinterpret_cast<float4*>(rbs + r * LDR + k) = v;
            }

            // gather xs rows (tf32); 2 slots per pass
#pragma unroll
            for (int kk = 0; kk < KMAXN; kk += 2) {
                int k = kk + (lane >> 4);
                int f = lane & 15;
                int s = __shfl_sync(0xffffffffu, src, k);
                float4 v = make_float4(0.f, 0.f, 0.f, 0.f);
                if (s >= 0) {
                    v = reinterpret_cast<const float4*>(g_xb + (size_t)s * PIN)[f];
                    tf32x4(v);
                }
                *reinterpret_cast<float4*>(xs + k * LDX + f * 4) = v;
            }
            __syncwarp();

            // 16 MMAs: rb[16,32] @ xs[32,64]
            wmma::fragment<wmma::accumulator, 16, 16, 8, float> c[4];
#pragma unroll
            for (int n = 0; n < 4; n++) wmma::fill_fragment(c[n], 0.0f);
#pragma unroll
            for (int k = 0; k < 4; k++) {
                wmma::fragment<wmma::matrix_a, 16, 16, 8, wmma::precision::tf32, wmma::row_major> a;
                wmma::load_matrix_sync(a, rbs + k * 8, LDR);
#pragma unroll
                for (int n = 0; n < 4; n++) {
                    wmma::fragment<wmma::matrix_b, 16, 16, 8, wmma::precision::tf32, wmma::row_major> b;
                    wmma::load_matrix_sync(b, xs + (k * 8) * LDX + n * 16, LDX);
                    wmma::mma_sync(c[n], a, b, c[n]);
                }
            }

            // tf32-round (matches R4's store->reload->convert path) and write
            // P row: element (r,d) -> offset r*64+d within the atom's row
            float* prow = P + (size_t)(w * 4 + i) * LDP;
#pragma unroll
            for (int n = 0; n < 4; n++) {
#pragma unroll
                for (int e = 0; e < c[n].num_elements; e++)
                    c[n].x[e] = wmma::__float_to_tf32(c[n].x[e]);
                wmma::store_matrix_sync(prow + n * 16, c[n], 64, wmma::mem_row_major);
            }
            __syncwarp();
        }
    }
    __syncthreads();

    // ---------------- stage 2 ----------------
    {
        float* Bs = U;                     // [64][LDBS], overlaps stage-1 buffers
        const int mi = w >> 2;             // 0..1 (M = 32 = 2 x 16)
        const int ni = w & 3;              // 0..3 (N = 64 = 4 x 16)

        wmma::fragment<wmma::accumulator, 16, 16, 8, float> c2;
        wmma::fill_fragment(c2, 0.0f);

        for (int k0 = 0; k0 < NRBF * PIN; k0 += 64) {
            // load W chunk [64,64] (tf32)
#pragma unroll
            for (int j = 0; j < 4; j++) {
                int row = (t >> 4) + j * 16;
                int col = (t & 15) * 4;
                float4 v = *reinterpret_cast<const float4*>(W_bil + (size_t)(k0 + row) * POUT + col);
                tf32x4(v);
                *reinterpret_cast<float4*>(Bs + row * LDBS + col) = v;
            }
            __syncthreads();

#pragma unroll
            for (int kk = 0; kk < 64; kk += 8) {
                wmma::fragment<wmma::matrix_a, 16, 16, 8, wmma::precision::tf32, wmma::row_major> a;
                wmma::fragment<wmma::matrix_b, 16, 16, 8, wmma::precision::tf32, wmma::row_major> b;
                wmma::load_matrix_sync(a, P + (size_t)(mi * 16) * LDP + k0 + kk, LDP);
                wmma::load_matrix_sync(b, Bs + kk * LDBS + ni * 16, LDBS);
                wmma::mma_sync(c2, a, b, c2);
            }
            __syncthreads();
        }

        const float s = *scale_p;
#pragma unroll
        for (int e = 0; e < c2.num_elements; e++) c2.x[e] *= s;

        // g_h2 padded to NPAD >= 1563*32, so no store guard needed
        wmma::store_matrix_sync(g_h2 + (size_t)(atom0 + mi * 16) * POUT + ni * 16,
                                c2, POUT, wmma::mem_row_major);
    }
}

// ---------------------------------------------------------------------------
// Launch
// ---------------------------------------------------------------------------
extern "C" void kernel_launch(void* const* d_in, const int* in_sizes, int n_in,
                              void* d_out, int out_size)
{
    const float* h         = (const float*)d_in[0];   // [50000,256]
    const float* rad_basis = (const float*)d_in[1];   // [50000,16,32]
    const int*   edge_idx  = (const int*)d_in[2];     // [2,1.6M] int32 OR int64
    const int*   tni       = (const int*)d_in[3];     // [1.6M]   int32 OR int64
    const float* W_down    = (const float*)d_in[4];   // [256,64]
    const float* W_bil     = (const float*)d_in[5];   // [1024,64]
    const float* W_up      = (const float*)d_in[6];   // [64,256]
    const float* scale     = (const float*)d_in[7];   // [1]
    float* out = (float*)d_out;                       // [50000,256]

    // Word stride per logical index element (int32 vs int64-as-pairs)
    int es = (in_sizes[2] >= 2 * NEDGES * 2) ? 2 : 1;
    int ts = (in_sizes[3] >= NEDGES * 2) ? 2 : 1;

    // Opt in to large dynamic smem for the fused kernel (idempotent, host-side)
    cudaFuncSetAttribute(fused_kernel, cudaFuncAttributeMaxDynamicSharedMemorySize, SMEM_BYTES);

    init_win_kernel<<<(NATOMS * KMAXN + 255) / 256, 256>>>();
    scatter_win_kernel<<<(NEDGES + 255) / 256, 256>>>(edge_idx, tni, es, ts);

    { dim3 grid(1, NPAD / 128);
      gemm1_kernel<<<grid, 256>>>(h, W_down); }

    { int nblk = (NATOMS + AT - 1) / AT;   // 1563
      fused_kernel<<<nblk, 256, SMEM_BYTES>>>(rad_basis, edge_idx, W_bil, scale, es); }

    { dim3 grid(EMB / 64, NPAD / 128);
      gemm3_kernel<<<grid, 256>>>(W_up, out); }
}

// round 6
// speedup vs baseline: 1.3797x; 1.3797x over previous
#include <cuda_runtime.h>
#include <mma.h>

using namespace nvcuda;

// Problem constants (fixed by the reference)
#define NATOMS  50000
#define EMB     256
#define PIN     64
#define POUT    64
#define NRBF    16
#define KMAXN   32
#define NEDGES  1600000
#define NPAD    50048          // 391 * 128 (padded row count for tile-exact GEMMs)

// Scratch (device globals — no allocation allowed; zero-initialized at load,
// padded rows are never written and stay zero)
__device__ float g_xb[NPAD * PIN];                      // silu(h @ W_down)
__device__ int   g_win[NATOMS * KMAXN];                 // winning edge id
__device__ float g_xba2[(size_t)NPAD * NRBF * PIN];     // einsum result
__device__ float g_h2[NPAD * POUT];                     // bilinear result

__device__ __forceinline__ float silu_f(float x) {
    return x / (1.0f + __expf(-x));
}

__device__ __forceinline__ unsigned f2tf32(float v) {
    unsigned u;
    asm("cvt.rna.tf32.f32 %0, %1;" : "=r"(u) : "f"(v));
    return u;
}

// ---------------------------------------------------------------------------
// Phase A: deterministic "last update wins" scatter (matches XLA .at[].set)
// ---------------------------------------------------------------------------
__global__ void init_win_kernel() {
    int i = blockIdx.x * blockDim.x + threadIdx.x;
    if (i < NATOMS * KMAXN) g_win[i] = -1;
}

__global__ void scatter_win_kernel(const int* __restrict__ ei,
                                   const int* __restrict__ tni,
                                   int es, int ts)
{
    int e = blockIdx.x * blockDim.x + threadIdx.x;
    if (e >= NEDGES) return;
    int dst = ei[(size_t)(NEDGES + e) * es];   // edge_index[1][e]
    int k   = tni[(size_t)e * ts];             // target_neighbor_idx[e]
    if ((unsigned)dst < NATOMS && (unsigned)k < KMAXN)
        atomicMax(&g_win[dst * KMAXN + k], e);
}

// ---------------------------------------------------------------------------
// tf32 wmma GEMM core (GEMM1 / GEMM2 / GEMM3): unchanged from R4
// ---------------------------------------------------------------------------
template<bool SILU, bool SCALE>
__device__ __forceinline__
void wgemm_core(const float* __restrict__ A, const float* __restrict__ B,
                float* __restrict__ C, int Mload, int Mstore,
                int ldb, int ldc, int K, const float* __restrict__ scale_p)
{
    constexpr int BM = 128, BN = 64, BK = 32;
    constexpr int LDA_ = BK + 4;
    constexpr int LDB_ = BN + 4;

    __shared__ __align__(16) float sraw[BM * LDB_];
    float* As = sraw;
    float* Bs = sraw + BM * LDA_;
    float* Cs = sraw;

    const int t  = threadIdx.x;
    const int m0 = blockIdx.y * BM;
    const int n0 = blockIdx.x * BN;
    const int warp = t >> 5;
    const int wm = (warp >> 1) * 32;
    const int wn = (warp & 1) * 32;

    wmma::fragment<wmma::accumulator, 16, 16, 8, float> c[2][2];
#pragma unroll
    for (int i = 0; i < 2; i++)
#pragma unroll
        for (int j = 0; j < 2; j++) wmma::fill_fragment(c[i][j], 0.0f);

    for (int k0 = 0; k0 < K; k0 += BK) {
#pragma unroll
        for (int i = 0; i < 4; i++) {
            int row = (t >> 3) + i * 32;
            int col = (t & 7) * 4;
            float4 v = make_float4(0.f, 0.f, 0.f, 0.f);
            int gm = m0 + row;
            if (gm < Mload)
                v = *reinterpret_cast<const float4*>(A + (size_t)gm * K + k0 + col);
            v.x = wmma::__float_to_tf32(v.x);
            v.y = wmma::__float_to_tf32(v.y);
            v.z = wmma::__float_to_tf32(v.z);
            v.w = wmma::__float_to_tf32(v.w);
            *reinterpret_cast<float4*>(As + row * LDA_ + col) = v;
        }
#pragma unroll
        for (int i = 0; i < 2; i++) {
            int row = (t >> 4) + i * 16;
            int col = (t & 15) * 4;
            float4 v = *reinterpret_cast<const float4*>(B + (size_t)(k0 + row) * ldb + n0 + col);
            v.x = wmma::__float_to_tf32(v.x);
            v.y = wmma::__float_to_tf32(v.y);
            v.z = wmma::__float_to_tf32(v.z);
            v.w = wmma::__float_to_tf32(v.w);
            *reinterpret_cast<float4*>(Bs + row * LDB_ + col) = v;
        }
        __syncthreads();

#pragma unroll
        for (int kk = 0; kk < BK; kk += 8) {
            wmma::fragment<wmma::matrix_a, 16, 16, 8, wmma::precision::tf32, wmma::row_major> a[2];
            wmma::fragment<wmma::matrix_b, 16, 16, 8, wmma::precision::tf32, wmma::row_major> b[2];
#pragma unroll
            for (int i = 0; i < 2; i++)
                wmma::load_matrix_sync(a[i], As + (wm + i * 16) * LDA_ + kk, LDA_);
#pragma unroll
            for (int j = 0; j < 2; j++)
                wmma::load_matrix_sync(b[j], Bs + kk * LDB_ + wn + j * 16, LDB_);
#pragma unroll
            for (int i = 0; i < 2; i++)
#pragma unroll
                for (int j = 0; j < 2; j++)
                    wmma::mma_sync(c[i][j], a[i], b[j], c[i][j]);
        }
        __syncthreads();
    }

    const float s = SCALE ? *scale_p : 1.0f;
#pragma unroll
    for (int i = 0; i < 2; i++)
#pragma unroll
        for (int j = 0; j < 2; j++)
#pragma unroll
            for (int e = 0; e < c[i][j].num_elements; e++) {
                float v = c[i][j].x[e] * s;
                if (SILU) v = silu_f(v);
                c[i][j].x[e] = v;
            }

    if (m0 + BM <= Mstore) {
#pragma unroll
        for (int i = 0; i < 2; i++)
#pragma unroll
            for (int j = 0; j < 2; j++)
                wmma::store_matrix_sync(C + (size_t)(m0 + wm + i * 16) * ldc + n0 + wn + j * 16,
                                        c[i][j], ldc, wmma::mem_row_major);
    } else {
#pragma unroll
        for (int i = 0; i < 2; i++)
#pragma unroll
            for (int j = 0; j < 2; j++)
                wmma::store_matrix_sync(Cs + (wm + i * 16) * LDB_ + wn + j * 16,
                                        c[i][j], LDB_, wmma::mem_row_major);
        __syncthreads();
        for (int idx = t; idx < BM * BN; idx += 256) {
            int r = idx >> 6, cc = idx & 63;
            if (m0 + r < Mstore)
                C[(size_t)(m0 + r) * ldc + n0 + cc] = Cs[r * LDB_ + cc];
        }
    }
}

// GEMM1: g_xb = silu(h @ W_down)     [50000,256] x [256,64]
__global__ __launch_bounds__(256)
void gemm1_kernel(const float* __restrict__ h, const float* __restrict__ W_down) {
    wgemm_core<true, false>(h, W_down, g_xb, NATOMS, NPAD, PIN, PIN, EMB, nullptr);
}

// GEMM2: g_h2 = (g_xba2 @ W_bilinear) * scale   [NPAD,1024] x [1024,64]
__global__ __launch_bounds__(256)
void gemm2_kernel(const float* __restrict__ W_bil, const float* __restrict__ scale) {
    wgemm_core<false, true>(g_xba2, W_bil, g_h2, NPAD, NPAD, POUT, POUT, NRBF * PIN, scale);
}

// GEMM3: out = silu(g_h2 @ W_up)     [NPAD,64] x [64,256], store 50000 rows
__global__ __launch_bounds__(256)
void gemm3_kernel(const float* __restrict__ W_up, float* __restrict__ out) {
    wgemm_core<true, false>(g_h2, W_up, out, NPAD, NATOMS, EMB, EMB, POUT, nullptr);
}

// ---------------------------------------------------------------------------
// Einsum v2: one warp per atom, raw mma.sync.m16n8k8 (tf32), B operands
// gathered DIRECTLY from global into fragment registers (no xs smem at all).
//   D[16 r, 64 d] = rb[16,32] @ xs[32,64],  xs[k,:] = g_xb[src[k],:]
// Fragment maps (PTX m16n8k8.row.col):
//   A: a0(r=l>>2, k=l&3) a1(r+8,k) a2(r,k+4) a3(r+8,k+4)
//   B: b0(k=l&3, n=l>>2) b1(k+4, n)
//   C: c0(r=l>>2, n=(l&3)*2) c1(n+1) c2(r+8,n) c3(r+8,n+1)
// ---------------------------------------------------------------------------
#define LDR 36   // rb row stride: 16B-aligned rows, conflict-free A reads

__global__ __launch_bounds__(256)
void einsum_kernel(const float* __restrict__ rad, const int* __restrict__ ei, int es)
{
    const int w    = threadIdx.x >> 5;
    const int lane = threadIdx.x & 31;
    const int atom = blockIdx.x * 8 + w;      // grid = 6250, exact

    __shared__ __align__(16) float rbs_all[8][NRBF * LDR];
    float* rbs = rbs_all[w];

    // winning source atom per neighbor slot (lane = slot), kept in a register
    int src = -1;
    {
        int e = g_win[atom * KMAXN + lane];
        if (e >= 0) {
            int s = ei[(size_t)e * es];       // edge_index[0][e]
            if ((unsigned)s < NATOMS) src = s;
        }
    }

    // stage rb[16][32] -> rbs (tf32-rounded), coalesced float4 in, float4 out
    {
        const float4* rg = reinterpret_cast<const float4*>(rad + (size_t)atom * NRBF * KMAXN);
#pragma unroll
        for (int j = 0; j < 4; j++) {
            int idx = lane + 32 * j;          // float4 index 0..127
            int g = idx * 4;
            int r = g >> 5, k = g & 31;
            float4 v = rg[idx];
            v.x = __uint_as_float(f2tf32(v.x));
            v.y = __uint_as_float(f2tf32(v.y));
            v.z = __uint_as_float(f2tf32(v.z));
            v.w = __uint_as_float(f2tf32(v.w));
            *reinterpret_cast<float4*>(rbs + r * LDR + k) = v;
        }
    }
    __syncwarp();

    // accumulators: 8 n-tiles (8 cols each) x 4 regs
    float acc[8][4];
#pragma unroll
    for (int n = 0; n < 8; n++)
#pragma unroll
        for (int j = 0; j < 4; j++) acc[n][j] = 0.0f;

    const int rA = lane >> 2;     // A row group
    const int kA = lane & 3;      // A/B k offset within chunk
    const int nB = lane >> 2;     // B col within n-tile

#pragma unroll
    for (int kc = 0; kc < 4; kc++) {
        // A operands from smem (conflict-free)
        unsigned a0 = __float_as_uint(rbs[rA * LDR + kA + kc * 8]);
        unsigned a1 = __float_as_uint(rbs[(rA + 8) * LDR + kA + kc * 8]);
        unsigned a2 = __float_as_uint(rbs[rA * LDR + kA + 4 + kc * 8]);
        unsigned a3 = __float_as_uint(rbs[(rA + 8) * LDR + kA + 4 + kc * 8]);

        // source rows for this k-chunk (2 per lane)
        int s0 = __shfl_sync(0xffffffffu, src, kA + kc * 8);
        int s1 = __shfl_sync(0xffffffffu, src, kA + 4 + kc * 8);
        const float* p0 = g_xb + (size_t)(s0 < 0 ? 0 : s0) * PIN + nB;
        const float* p1 = g_xb + (size_t)(s1 < 0 ? 0 : s1) * PIN + nB;

        // gather B straight into registers: per n-tile one 100%-sector load pair
        float bv0[8], bv1[8];
#pragma unroll
        for (int n = 0; n < 8; n++) {
            bv0[n] = (s0 >= 0) ? p0[n * 8] : 0.0f;
            bv1[n] = (s1 >= 0) ? p1[n * 8] : 0.0f;
        }
#pragma unroll
        for (int n = 0; n < 8; n++) {
            unsigned b0 = f2tf32(bv0[n]);
            unsigned b1 = f2tf32(bv1[n]);
            asm volatile(
                "mma.sync.aligned.m16n8k8.row.col.f32.tf32.tf32.f32 "
                "{%0,%1,%2,%3},{%4,%5,%6,%7},{%8,%9},{%0,%1,%2,%3};"
                : "+f"(acc[n][0]), "+f"(acc[n][1]), "+f"(acc[n][2]), "+f"(acc[n][3])
                : "r"(a0), "r"(a1), "r"(a2), "r"(a3), "r"(b0), "r"(b1));
        }
    }

    // write x_ba2[atom]: [16 r][64 d] row-major; float2 stores, full sectors
    float* outp = g_xba2 + (size_t)atom * NRBF * PIN;
    const int cC = (lane & 3) * 2;
#pragma unroll
    for (int n = 0; n < 8; n++) {
        *reinterpret_cast<float2*>(outp + rA * PIN + n * 8 + cC)
            = make_float2(acc[n][0], acc[n][1]);
        *reinterpret_cast<float2*>(outp + (rA + 8) * PIN + n * 8 + cC)
            = make_float2(acc[n][2], acc[n][3]);
    }
}

// ---------------------------------------------------------------------------
// Launch — kernel launches ONLY (graph-capturable)
// ---------------------------------------------------------------------------
extern "C" void kernel_launch(void* const* d_in, const int* in_sizes, int n_in,
                              void* d_out, int out_size)
{
    const float* h         = (const float*)d_in[0];   // [50000,256]
    const float* rad_basis = (const float*)d_in[1];   // [50000,16,32]
    const int*   edge_idx  = (const int*)d_in[2];     // [2,1.6M] int32 OR int64
    const int*   tni       = (const int*)d_in[3];     // [1.6M]   int32 OR int64
    const float* W_down    = (const float*)d_in[4];   // [256,64]
    const float* W_bil     = (const float*)d_in[5];   // [1024,64]
    const float* W_up      = (const float*)d_in[6];   // [64,256]
    const float* scale     = (const float*)d_in[7];   // [1]
    float* out = (float*)d_out;                       // [50000,256]

    // Word stride per logical index element (int32 vs int64-as-pairs)
    int es = (in_sizes[2] >= 2 * NEDGES * 2) ? 2 : 1;
    int ts = (in_sizes[3] >= NEDGES * 2) ? 2 : 1;

    init_win_kernel<<<(NATOMS * KMAXN + 255) / 256, 256>>>();
    scatter_win_kernel<<<(NEDGES + 255) / 256, 256>>>(edge_idx, tni, es, ts);

    { dim3 grid(1, NPAD / 128);
      gemm1_kernel<<<grid, 256>>>(h, W_down); }

    einsum_kernel<<<NATOMS / 8, 256>>>(rad_basis, edge_idx, es);

    { dim3 grid(1, NPAD / 128);
      gemm2_kernel<<<grid, 256>>>(W_bil, scale); }

    { dim3 grid(EMB / 64, NPAD / 128);
      gemm3_kernel<<<grid, 256>>>(W_up, out); }
}